// round 4
// baseline (speedup 1.0000x reference)
#include <cuda_runtime.h>
#include <math.h>

// ---------------- problem constants ----------------
#define NB    4
#define NS    3
#define NE    7
#define IMGSZ 256
#define PHS   8
#define HS    32      // IMG/PH
#define DMODEL 128
#define NHEAD 4
#define DKK   64
#define DCC   128
#define DHH   32
#define TEMBN 256
#define LKN   128
#define NGRP  16
#define EPSV  1e-5f

// ---------------- scratch (__device__ globals, zero-init; borders never written) --
__device__ float g_xp_pad[12 * 448 * 34 * 34];   // patchified, padded
__device__ float g_conv1 [12 * 128 * 32 * 32];   // conv1 out (= xp in (B,S,D,H,H))
__device__ float g_xn    [12 * 128 * 32 * 32];   // groupnormed
__device__ float g_q     [4096 * 256];           // q2 (Nq, NH*DK)
__device__ float g_oattn [4096 * 128];           // attention out, (Nq, DC) layout
__device__ float g_o2pad [4 * 128 * 34 * 34];    // outproj out, padded for conv2
__device__ float g_u     [4 * 7 * 256 * 256];    // unpatchified image (skip)
__device__ float g_cmod  [64];                   // modulation c (4 x 14)
__device__ float g_psum  [128];
__device__ float g_psq   [128];
__device__ float g_stats [8];                    // per-batch mean, inv_std

// ---------------- helpers ----------------
__device__ __forceinline__ float geluf(float v) {
    return 0.5f * v * (1.0f + erff(v * 0.70710678118654752f));
}

// ---------------- 1) pack x -> padded patchified layout (12,448,34,34) ----------
__global__ void k_pack(const float* __restrict__ x) {
    int idx = blockIdx.x * 256 + threadIdx.x;
    if (idx >= 12 * 448 * 34 * 34) return;
    int xx = idx % 34;
    int t  = idx / 34;
    int yy = t % 34;  t /= 34;
    int c  = t % 448;
    int n  = t / 448;
    float v = 0.f;
    if (xx > 0 && xx < 33 && yy > 0 && yy < 33) {
        int y = yy - 1, xq = xx - 1;
        int p1 = c / 56, rem = c % 56, p2 = rem / 7, e = rem % 7;
        v = x[((n * 7 + e) * 256 + (y * 8 + p1)) * 256 + (xq * 8 + p2)];
    }
    g_xp_pad[idx] = v;
}

// ---------------- 2/7) direct 3x3 conv (GEMM-style, smem staged per channel) ----
// MODE 1: conv1  (in=g_xp_pad Cin=448, out=g_conv1 Cout=128, +pos_embed)
// MODE 2: conv2  (in=g_o2pad  Cin=128, out=g_u unpatchified Cout=448)
template<int TM, int MODE>
__global__ void k_conv3x3(const float* __restrict__ wgt,
                          const float* __restrict__ bias,
                          const float* __restrict__ pos,
                          int Cin, int Cout) {
    const int CT = TM * 16;
    __shared__ float sW[CT * 9];
    __shared__ float sIn[3 * 34];

    const float* inp = (MODE == 1) ? g_xp_pad : g_o2pad;
    int y  = blockIdx.x;
    int m0 = blockIdx.y * CT;
    int n  = blockIdx.z;
    int tid = threadIdx.x;            // 128 threads
    int tx = tid & 7;                 // 8 pixel groups of 4
    int ty = tid >> 3;                // 16 out-channel groups of TM

    float acc[TM][4];
#pragma unroll
    for (int i = 0; i < TM; i++)
#pragma unroll
        for (int j = 0; j < 4; j++) acc[i][j] = 0.f;

    const float* inbase = inp + (size_t)n * Cin * 1156 + y * 34;

    for (int c = 0; c < Cin; c++) {
        __syncthreads();
        if (tid < 102) sIn[tid] = inbase[c * 1156 + tid];       // rows y..y+2 contiguous
        for (int i = tid; i < CT * 9; i += 128)
            sW[i] = wgt[((m0 + i / 9) * Cin + c) * 9 + (i % 9)];
        __syncthreads();

        float rin[3][6];
#pragma unroll
        for (int r = 0; r < 3; r++)
#pragma unroll
            for (int j = 0; j < 6; j++) rin[r][j] = sIn[r * 34 + tx * 4 + j];

#pragma unroll
        for (int tm = 0; tm < TM; tm++) {
            float w9[9];
#pragma unroll
            for (int t9 = 0; t9 < 9; t9++) w9[t9] = sW[(ty * TM + tm) * 9 + t9];
#pragma unroll
            for (int ky = 0; ky < 3; ky++)
#pragma unroll
                for (int kx = 0; kx < 3; kx++) {
                    float wv = w9[ky * 3 + kx];
#pragma unroll
                    for (int j = 0; j < 4; j++)
                        acc[tm][j] = fmaf(wv, rin[ky][j + kx], acc[tm][j]);
                }
        }
    }

#pragma unroll
    for (int tm = 0; tm < TM; tm++) {
        int o = m0 + ty * TM + tm;
        float bv = bias[o];
#pragma unroll
        for (int j = 0; j < 4; j++) {
            int xq = tx * 4 + j;
            float v = acc[tm][j] + bv;
            if (MODE == 1) {
                v += pos[o * 1024 + y * 32 + xq];
                g_conv1[((n * 128 + o) * 32 + y) * 32 + xq] = v;
            } else {
                int p1 = o / 56, rem = o % 56, p2 = rem / 7, e = rem % 7;
                g_u[(((size_t)n * 7 + e) * 256 + (y * 8 + p1)) * 256 + (xq * 8 + p2)] = v;
            }
        }
    }
}

// ---------------- 3) group norm (contiguous 24576-float chunks) ----------------
__global__ void k_gnorm(const float* __restrict__ gamma, const float* __restrict__ beta) {
    int b = blockIdx.x >> 4, g = blockIdx.x & 15;
    const int CH = 24576;
    size_t base = (size_t)b * 393216 + (size_t)g * CH;
    int tid = threadIdx.x;    // 256
    float s = 0.f, sq = 0.f;
    for (int i = tid; i < CH; i += 256) {
        float v = g_conv1[base + i];
        s += v; sq += v * v;
    }
#pragma unroll
    for (int off = 16; off; off >>= 1) {
        s  += __shfl_xor_sync(0xffffffffu, s,  off);
        sq += __shfl_xor_sync(0xffffffffu, sq, off);
    }
    __shared__ float rs[8], rq[8];
    int w = tid >> 5, lane = tid & 31;
    if (!lane) { rs[w] = s; rq[w] = sq; }
    __syncthreads();
    s = 0.f; sq = 0.f;
#pragma unroll
    for (int i = 0; i < 8; i++) { s += rs[i]; sq += rq[i]; }
    float mean = s / (float)CH;
    float var  = sq / (float)CH - mean * mean;
    float inv  = rsqrtf(var + EPSV);
    for (int i = tid; i < CH; i += 256) {
        int dch = g * 8 + i / 3072;
        g_xn[base + i] = (g_conv1[base + i] - mean) * inv * gamma[dch] + beta[dch];
    }
}

// ---------------- 4) q GEMM: (4096 x 256) = xn_rows(4096x384) @ w_eff^T --------
__global__ void k_qgemm(const float* __restrict__ w1, const float* __restrict__ b1,
                        const float* __restrict__ w2, const float* __restrict__ b2) {
    __shared__ float sA[32][65];
    __shared__ float sB[32][65];
    int n0 = blockIdx.x * 64, o0 = blockIdx.y * 64;
    int tid = threadIdx.x;   // 256
    float sw[3] = { w2[0], w2[1], w2[2] };
    float sws = sw[0] + sw[1] + sw[2];
    int tx = tid % 16, ty = tid / 16;
    float acc[4][4];
#pragma unroll
    for (int i = 0; i < 4; i++)
#pragma unroll
        for (int j = 0; j < 4; j++) acc[i][j] = 0.f;

    for (int kk = 0; kk < 384; kk += 32) {
        __syncthreads();
        for (int i = tid; i < 2048; i += 256) {
            int nl = i >> 5, kl = i & 31;
            sA[kl][nl] = g_xn[(size_t)(n0 + nl) * 384 + kk + kl];
        }
        for (int i = tid; i < 2048; i += 256) {
            int ol = i & 63, kl = i >> 6;
            int kg = kk + kl;
            sB[kl][ol] = w1[(o0 + ol) * 128 + kg / 3] * sw[kg % 3];
        }
        __syncthreads();
#pragma unroll
        for (int k = 0; k < 32; k++) {
            float a[4], bb[4];
#pragma unroll
            for (int j = 0; j < 4; j++) { a[j] = sA[k][ty * 4 + j]; bb[j] = sB[k][tx * 4 + j]; }
#pragma unroll
            for (int i = 0; i < 4; i++)
#pragma unroll
                for (int j = 0; j < 4; j++) acc[i][j] = fmaf(a[i], bb[j], acc[i][j]);
        }
    }
    float fb = b2[0];
#pragma unroll
    for (int i = 0; i < 4; i++)
#pragma unroll
        for (int j = 0; j < 4; j++) {
            int o = o0 + tx * 4 + j;
            g_q[(n0 + ty * 4 + i) * 256 + o] = acc[i][j] + b1[o] * sws + fb;
        }
}

// ---------------- 5) attention (one block per row r) ---------------------------
__global__ void k_attn(const float* __restrict__ kc, const float* __restrict__ vc) {
    int r = blockIdx.x;
    int tid = threadIdx.x;     // 128
    int w = tid >> 5, lane = tid & 31;
    __shared__ float sq[64];
    __shared__ float se[128];
    __shared__ float red[4], red2[4];
    __shared__ float oacc[4][32];

    if (tid < 64) sq[tid] = g_q[r * 64 + tid];
    __syncthreads();

    // score for l = tid
    const float4* krow = (const float4*)(kc + (size_t)r * 8192 + (size_t)tid * 64);
    float dot = 0.f;
#pragma unroll
    for (int i = 0; i < 16; i++) {
        float4 kv = krow[i];
        dot += kv.x * sq[i * 4] + kv.y * sq[i * 4 + 1] + kv.z * sq[i * 4 + 2] + kv.w * sq[i * 4 + 3];
    }
    dot *= 0.125f;

    float m = dot;
#pragma unroll
    for (int off = 16; off; off >>= 1) m = fmaxf(m, __shfl_xor_sync(0xffffffffu, m, off));
    if (!lane) red[w] = m;
    __syncthreads();
    m = fmaxf(fmaxf(red[0], red[1]), fmaxf(red[2], red[3]));

    float e = __expf(dot - m);
    se[tid] = e;
    float s = e;
#pragma unroll
    for (int off = 16; off; off >>= 1) s += __shfl_xor_sync(0xffffffffu, s, off);
    if (!lane) red2[w] = s;
    __syncthreads();                       // also publishes se[]
    float inv = 1.f / (red2[0] + red2[1] + red2[2] + red2[3]);

    // o[c] accumulation: warp w handles l in [w*32, w*32+32), lane = c
    const float* vbase = vc + (size_t)r * 4096;
    float a = 0.f;
#pragma unroll 4
    for (int li = 0; li < 32; li++) {
        int l = w * 32 + li;
        a = fmaf(se[l], vbase[l * 32 + lane], a);
    }
    oacc[w][lane] = a;
    __syncthreads();
    if (tid < 32) {
        float tot = oacc[0][tid] + oacc[1][tid] + oacc[2][tid] + oacc[3][tid];
        g_oattn[(r & 4095) * 128 + (r >> 12) * 32 + tid] = tot * inv;
    }
}

// ---------------- 6) out projection -> padded conv2 input ----------------------
__global__ void k_outproj(const float* __restrict__ w, const float* __restrict__ bias) {
    __shared__ float sIn[32][129];
    __shared__ float sWt[32][129];
    int b = blockIdx.y;
    int hw0 = blockIdx.x * 128;
    int tid = threadIdx.x;    // 256
    int tx = tid % 16, ty = tid / 16;
    float acc[8][8];
#pragma unroll
    for (int i = 0; i < 8; i++)
#pragma unroll
        for (int j = 0; j < 8; j++) acc[i][j] = 0.f;

    for (int cc = 0; cc < 128; cc += 32) {
        __syncthreads();
        for (int i = tid; i < 4096; i += 256) {
            int kl = i >> 7, hl = i & 127;
            sIn[kl][hl] = g_oattn[b * 131072 + (cc + kl) * 1024 + hw0 + hl];
        }
        for (int i = tid; i < 4096; i += 256) {
            int ol = i & 127, kl = i >> 7;
            sWt[kl][ol] = w[ol * 128 + cc + kl];
        }
        __syncthreads();
#pragma unroll 8
        for (int k = 0; k < 32; k++) {
            float a[8], bb[8];
#pragma unroll
            for (int i = 0; i < 8; i++) { a[i] = sWt[k][ty * 8 + i]; bb[i] = sIn[k][tx * 8 + i]; }
#pragma unroll
            for (int i = 0; i < 8; i++)
#pragma unroll
                for (int j = 0; j < 8; j++) acc[i][j] = fmaf(a[i], bb[j], acc[i][j]);
        }
    }
#pragma unroll
    for (int i = 0; i < 8; i++) {
        int o = ty * 8 + i;
        float bv = bias[o];
#pragma unroll
        for (int j = 0; j < 8; j++) {
            int hw = hw0 + tx * 8 + j;
            int y = hw >> 5, x2 = hw & 31;
            g_o2pad[((b * 128 + o) * 34 + y + 1) * 34 + x2 + 1] = acc[i][j] + bv;
        }
    }
}

// ---------------- 8) modulation c = silu(emb) @ mod_w^T + mod_b ----------------
__global__ void k_cmod(const float* __restrict__ emb, const float* __restrict__ mw,
                       const float* __restrict__ mb) {
    int t = threadIdx.x;
    if (t >= 56) return;
    int b = t / 14, j = t % 14;
    float acc = mb[j];
    for (int i = 0; i < 256; i++) {
        float v = emb[b * 256 + i];
        float sil = v / (1.f + __expf(-v));
        acc = fmaf(sil, mw[j * 256 + i], acc);
    }
    g_cmod[t] = acc;
}

// ---------------- 9/10) per-batch stats of u -----------------------------------
__global__ void k_upart() {
    int b = blockIdx.y, blk = blockIdx.x;       // 32 blocks per batch
    size_t base = (size_t)b * 458752 + (size_t)blk * 14336;
    int tid = threadIdx.x;  // 256
    float s = 0.f, sq = 0.f;
    for (int i = tid; i < 14336; i += 256) {
        float v = g_u[base + i];
        s += v; sq += v * v;
    }
#pragma unroll
    for (int off = 16; off; off >>= 1) {
        s  += __shfl_xor_sync(0xffffffffu, s,  off);
        sq += __shfl_xor_sync(0xffffffffu, sq, off);
    }
    __shared__ float rs[8], rq[8];
    int w = tid >> 5, lane = tid & 31;
    if (!lane) { rs[w] = s; rq[w] = sq; }
    __syncthreads();
    if (tid == 0) {
        float ts = 0.f, tq = 0.f;
#pragma unroll
        for (int i = 0; i < 8; i++) { ts += rs[i]; tq += rq[i]; }
        g_psum[b * 32 + blk] = ts;
        g_psq [b * 32 + blk] = tq;
    }
}

__global__ void k_ucomb() {
    int b = threadIdx.x;
    if (b < 4) {
        float s = 0.f, sq = 0.f;
        for (int i = 0; i < 32; i++) { s += g_psum[b * 32 + i]; sq += g_psq[b * 32 + i]; }
        float mean = s / 458752.f;
        float var  = sq / 458752.f - mean * mean;
        g_stats[b * 2]     = mean;
        g_stats[b * 2 + 1] = rsqrtf(var + EPSV);
    }
}

// ---------------- 11) final fused elementwise ----------------------------------
__global__ void k_final(const float* __restrict__ ew, const float* __restrict__ eb,
                        const float* __restrict__ fw, const float* __restrict__ fb,
                        float* __restrict__ out) {
    int b = blockIdx.y;
    int p = blockIdx.x * 256 + threadIdx.x;   // 65536 px per batch
    __shared__ float s_ew[98], s_eb[14], s_fw[49], s_fb[7], s_sc[7], s_sh[7];
    __shared__ float s_mean, s_istd;
    int t = threadIdx.x;
    if (t < 98) s_ew[t] = ew[t];
    if (t < 49) s_fw[t] = fw[t];
    if (t < 14) s_eb[t] = eb[t];
    if (t < 7)  { s_fb[t] = fb[t]; s_sc[t] = g_cmod[b * 14 + t]; s_sh[t] = g_cmod[b * 14 + 7 + t]; }
    if (t == 0) { s_mean = g_stats[b * 2]; s_istd = g_stats[b * 2 + 1]; }
    __syncthreads();

    float mean = s_mean, istd = s_istd;
    float uv[7], un[7];
#pragma unroll
    for (int e = 0; e < 7; e++) uv[e] = g_u[((size_t)b * 7 + e) * 65536 + p];
#pragma unroll
    for (int e = 0; e < 7; e++) un[e] = (uv[e] - mean) * istd * (1.f + s_sc[e]) + s_sh[e];

    float en[14];
#pragma unroll
    for (int j = 0; j < 14; j++) {
        float a = s_eb[j];
#pragma unroll
        for (int e = 0; e < 7; e++) a = fmaf(s_ew[j * 7 + e], un[e], a);
        en[j] = a;
    }
    float hf[7];
#pragma unroll
    for (int e = 0; e < 7; e++) hf[e] = geluf(un[e]) + en[e] * geluf(en[7 + e]);

#pragma unroll
    for (int o = 0; o < 7; o++) {
        float a = s_fb[o];
#pragma unroll
        for (int e = 0; e < 7; e++) a = fmaf(s_fw[o * 7 + e], hf[e], a);
        out[((size_t)b * 7 + o) * 65536 + p] = a + uv[o];
    }
}

// ---------------- launch --------------------------------------------------------
extern "C" void kernel_launch(void* const* d_in, const int* in_sizes, int n_in,
                              void* d_out, int out_size) {
    const float* x         = (const float*)d_in[0];
    const float* k_cond    = (const float*)d_in[1];
    const float* v_cond    = (const float*)d_in[2];
    const float* emb       = (const float*)d_in[3];
    const float* pos_embed = (const float*)d_in[4];
    const float* patch_w   = (const float*)d_in[5];
    const float* patch_b   = (const float*)d_in[6];
    const float* gn_gamma  = (const float*)d_in[7];
    const float* gn_beta   = (const float*)d_in[8];
    const float* fc1q_w    = (const float*)d_in[9];
    const float* fc1q_b    = (const float*)d_in[10];
    const float* fc2q_w    = (const float*)d_in[11];
    const float* fc2q_b    = (const float*)d_in[12];
    const float* outproj_w = (const float*)d_in[13];
    const float* outproj_b = (const float*)d_in[14];
    const float* unpatch_w = (const float*)d_in[15];
    const float* unpatch_b = (const float*)d_in[16];
    const float* mod_w     = (const float*)d_in[17];
    const float* mod_b     = (const float*)d_in[18];
    const float* enlarge_w = (const float*)d_in[19];
    const float* enlarge_b = (const float*)d_in[20];
    const float* ff2_w     = (const float*)d_in[21];
    const float* ff2_b     = (const float*)d_in[22];
    float* out = (float*)d_out;

    k_pack<<<24276, 256>>>(x);
    k_conv3x3<8, 1><<<dim3(32, 1, 12), 128>>>(patch_w, patch_b, pos_embed, 448, 128);
    k_gnorm<<<64, 256>>>(gn_gamma, gn_beta);
    k_qgemm<<<dim3(64, 4), 256>>>(fc1q_w, fc1q_b, fc2q_w, fc2q_b);
    k_attn<<<16384, 128>>>(k_cond, v_cond);
    k_outproj<<<dim3(8, 4), 256>>>(outproj_w, outproj_b);
    k_conv3x3<7, 2><<<dim3(32, 4, 4), 128>>>(unpatch_w, unpatch_b, (const float*)0, 128, 448);
    k_cmod<<<1, 64>>>(emb, mod_w, mod_b);
    k_upart<<<dim3(32, 4), 256>>>();
    k_ucomb<<<1, 32>>>();
    k_final<<<dim3(256, 4), 256>>>(enlarge_w, enlarge_b, ff2_w, ff2_b, out);
}

// round 5
// speedup vs baseline: 2.2442x; 2.2442x over previous
#include <cuda_runtime.h>
#include <cuda_bf16.h>
#include <math.h>

#define EPSV 1e-5f

// ---------------- scratch (__device__ globals; zero-init borders load-bearing) --
__device__ __nv_bfloat16 g_xph[12*448*34*34];
__device__ __nv_bfloat16 g_xpl[12*448*34*34];
__device__ __nv_bfloat16 g_w1h[9*128*448];
__device__ __nv_bfloat16 g_w1l[9*128*448];
__device__ __nv_bfloat16 g_w2h[9*448*128];
__device__ __nv_bfloat16 g_w2l[9*448*128];
__device__ __nv_bfloat16 g_wqh[256*384];
__device__ __nv_bfloat16 g_wql[256*384];
__device__ __nv_bfloat16 g_woh[128*128];
__device__ __nv_bfloat16 g_wol[128*128];
__device__ float         g_conv1[12*128*1024];
__device__ __nv_bfloat16 g_xnh[12*128*1024];
__device__ __nv_bfloat16 g_xnl[12*128*1024];
__device__ float         g_q[4096*256];
__device__ __nv_bfloat16 g_oah[4*1024*128];    // attn out transposed [b][hw][C]
__device__ __nv_bfloat16 g_oal[4*1024*128];
__device__ __nv_bfloat16 g_o2h[4*128*34*34];   // padded conv2 input
__device__ __nv_bfloat16 g_o2l[4*128*34*34];
__device__ float         g_u[4*7*65536];
__device__ float g_cmod[64];
__device__ float g_psum[128], g_psq[128], g_stats[8];

// ---------------- helpers ----------------
__device__ __forceinline__ void split2(float v, __nv_bfloat16* h, __nv_bfloat16* l) {
    __nv_bfloat16 hh = __float2bfloat16(v);
    *h = hh;
    *l = __float2bfloat16(v - __bfloat162float(hh));
}
__device__ __forceinline__ float geluf(float v) {
    return 0.5f * v * (1.0f + erff(v * 0.70710678118654752f));
}
__device__ __forceinline__ unsigned ldb2(const __nv_bfloat16* p) {
    return *reinterpret_cast<const unsigned*>(p);
}
__device__ __forceinline__ void mma16816(float* c, unsigned a0, unsigned a1, unsigned a2, unsigned a3,
                                         unsigned b0, unsigned b1) {
    asm volatile("mma.sync.aligned.m16n8k16.row.col.f32.bf16.bf16.f32 "
        "{%0,%1,%2,%3}, {%4,%5,%6,%7}, {%8,%9}, {%0,%1,%2,%3};\n"
        : "+f"(c[0]), "+f"(c[1]), "+f"(c[2]), "+f"(c[3])
        : "r"(a0), "r"(a1), "r"(a2), "r"(a3), "r"(b0), "r"(b1));
}

// ---------------- 1) pack x -> padded patchified bf16 hi/lo --------------------
__global__ void k_pack(const float* __restrict__ x) {
    int t = blockIdx.x * 256 + threadIdx.x;
    if (t >= 688128) return;                 // 84 * 256 * 32
    int xq = t & 31;
    int Y  = (t >> 5) & 255;
    int ne = t >> 13;                        // n*7+e in [0,84)
    int y = Y >> 3, p1 = Y & 7;
    const float4* src = reinterpret_cast<const float4*>(x + ((size_t)ne * 256 + Y) * 256 + xq * 8);
    float4 f0 = src[0], f1 = src[1];
    float vals[8] = {f0.x, f0.y, f0.z, f0.w, f1.x, f1.y, f1.z, f1.w};
    int n = ne / 7, e = ne % 7;
#pragma unroll
    for (int p2 = 0; p2 < 8; p2++) {
        int c = p1 * 56 + p2 * 7 + e;
        size_t d = (((size_t)n * 448 + c) * 34 + y + 1) * 34 + xq + 1;
        split2(vals[p2], &g_xph[d], &g_xpl[d]);
    }
}

// ---------------- weight packs --------------------------------------------------
__global__ void k_packw1(const float* __restrict__ w) {   // -> [tap][m=128][c=448]
    int i = blockIdx.x * 256 + threadIdx.x;
    if (i >= 9 * 128 * 448) return;
    int c = i % 448; int t2 = i / 448; int m = t2 % 128; int tap = t2 / 128;
    split2(w[(m * 448 + c) * 9 + tap], &g_w1h[i], &g_w1l[i]);
}
__global__ void k_packw2(const float* __restrict__ w) {   // -> [tap][o=448][c=128]
    int i = blockIdx.x * 256 + threadIdx.x;
    if (i >= 9 * 448 * 128) return;
    int c = i % 128; int t2 = i / 128; int o = t2 % 448; int tap = t2 / 448;
    split2(w[(o * 128 + c) * 9 + tap], &g_w2h[i], &g_w2l[i]);
}
__global__ void k_packwq(const float* __restrict__ w1, const float* __restrict__ w2) {
    int i = blockIdx.x * 256 + threadIdx.x;               // weff[m=256][k=384], k=d*3+s
    if (i >= 256 * 384) return;
    int m = i / 384, k = i % 384;
    split2(w1[m * 128 + k / 3] * w2[k % 3], &g_wqh[i], &g_wql[i]);
}
__global__ void k_packwo(const float* __restrict__ w) {   // [o=128][c=128]
    int i = blockIdx.x * 256 + threadIdx.x;
    if (i >= 128 * 128) return;
    split2(w[i], &g_woh[i], &g_wol[i]);
}

// ---------------- 2/7) conv3x3 as implicit GEMM on bf16 hi/lo mma ---------------
// MODE 1: conv1 (g_xp -> g_conv1 fp32, +pos)   MODE 2: conv2 (g_o2 -> g_u unpatch)
// Tile: M = WARPS*16 out-chans, N = NROWS*32 = NT*8 pixels.
template<int CIN, int COUT, int WARPS, int NT, int NROWS, int MODE>
__global__ void __launch_bounds__(WARPS*32) k_convmma(const float* __restrict__ bias,
                                                      const float* __restrict__ pos) {
    const int R = NROWS + 2;
    __shared__ __nv_bfloat16 sh[R * 34 * 18];
    __shared__ __nv_bfloat16 sl[R * 34 * 18];
    const __nv_bfloat16* inh = (MODE == 1) ? g_xph : g_o2h;
    const __nv_bfloat16* inl = (MODE == 1) ? g_xpl : g_o2l;
    const __nv_bfloat16* wph = (MODE == 1) ? g_w1h : g_w2h;
    const __nv_bfloat16* wpl = (MODE == 1) ? g_w1l : g_w2l;
    int y0  = blockIdx.x * NROWS;
    int m0  = blockIdx.y * (WARPS * 16);
    int img = blockIdx.z;
    int tid = threadIdx.x, lane = tid & 31, warp = tid >> 5;
    int q2 = (lane & 3) * 2, gp = lane >> 2;

    float acc[NT][4];
#pragma unroll
    for (int a = 0; a < NT; a++)
#pragma unroll
        for (int c = 0; c < 4; c++) acc[a][c] = 0.f;

    size_t inbase = (size_t)img * CIN * 1156 + (size_t)y0 * 34;
    const int ELEMS = R * 34 * 16;
    int m = m0 + warp * 16 + gp;

    for (int c0 = 0; c0 < CIN; c0 += 16) {
        __syncthreads();
        for (int i = tid; i < ELEMS; i += WARPS * 32) {
            int c = i / (R * 34), rc = i % (R * 34);
            int dst = rc * 18 + c;
            size_t src = inbase + (size_t)(c0 + c) * 1156 + rc;
            sh[dst] = inh[src];
            sl[dst] = inl[src];
        }
        __syncthreads();

#pragma unroll
        for (int tap = 0; tap < 9; tap++) {
            int ky = tap / 3, kx = tap % 3;
            const __nv_bfloat16* wb = wph + (size_t)(tap * COUT + m) * CIN + c0;
            const __nv_bfloat16* wl = wpl + (size_t)(tap * COUT + m) * CIN + c0;
            unsigned a0 = ldb2(wb + q2),            a1 = ldb2(wb + 8 * CIN + q2);
            unsigned a2 = ldb2(wb + q2 + 8),        a3 = ldb2(wb + 8 * CIN + q2 + 8);
            unsigned l0 = ldb2(wl + q2),            l1 = ldb2(wl + 8 * CIN + q2);
            unsigned l2 = ldb2(wl + q2 + 8),        l3 = ldb2(wl + 8 * CIN + q2 + 8);
#pragma unroll
            for (int nt = 0; nt < NT; nt++) {
                int n = nt * 8 + gp;
                int ad = (((n >> 5) + ky) * 34 + (n & 31) + kx) * 18 + q2;
                unsigned bh0 = ldb2(&sh[ad]), bh1 = ldb2(&sh[ad + 8]);
                unsigned bl0 = ldb2(&sl[ad]), bl1 = ldb2(&sl[ad + 8]);
                mma16816(acc[nt], a0, a1, a2, a3, bh0, bh1);
                mma16816(acc[nt], l0, l1, l2, l3, bh0, bh1);
                mma16816(acc[nt], a0, a1, a2, a3, bl0, bl1);
            }
        }
    }

    float bv0 = bias[m], bv1 = bias[m + 8];
#pragma unroll
    for (int nt = 0; nt < NT; nt++) {
        int n  = nt * 8 + q2;
        int yo = y0 + (n >> 5);
        int x  = n & 31;
        float v0 = acc[nt][0] + bv0;
        float v1 = acc[nt][1] + bv0;
        float v2 = acc[nt][2] + bv1;
        float v3 = acc[nt][3] + bv1;
        if (MODE == 1) {
            v0 += pos[m * 1024 + yo * 32 + x];
            v1 += pos[m * 1024 + yo * 32 + x + 1];
            v2 += pos[(m + 8) * 1024 + yo * 32 + x];
            v3 += pos[(m + 8) * 1024 + yo * 32 + x + 1];
            *reinterpret_cast<float2*>(&g_conv1[((img * 128 + m) * 32 + yo) * 32 + x])     = make_float2(v0, v1);
            *reinterpret_cast<float2*>(&g_conv1[((img * 128 + m + 8) * 32 + yo) * 32 + x]) = make_float2(v2, v3);
        } else {
            int o = m;
            int p1i = o / 56, rem = o % 56, p2i = rem / 7, e = rem % 7;
            size_t base = (((size_t)img * 7 + e) * 256 + yo * 8 + p1i) * 256;
            g_u[base + x * 8 + p2i]       = v0;
            g_u[base + (x + 1) * 8 + p2i] = v1;
            o = m + 8;
            p1i = o / 56; rem = o % 56; p2i = rem / 7; e = rem % 7;
            base = (((size_t)img * 7 + e) * 256 + yo * 8 + p1i) * 256;
            g_u[base + x * 8 + p2i]       = v2;
            g_u[base + (x + 1) * 8 + p2i] = v3;
        }
    }
}

// ---------------- 3) group norm -> bf16 hi/lo -----------------------------------
__global__ void k_gnorm(const float* __restrict__ gamma, const float* __restrict__ beta) {
    int b = blockIdx.x >> 4, g = blockIdx.x & 15;
    const int CH = 24576;
    size_t base = (size_t)b * 393216 + (size_t)g * CH;
    int tid = threadIdx.x;
    float s = 0.f, sq = 0.f;
    for (int i = tid; i < CH; i += 256) {
        float v = g_conv1[base + i];
        s += v; sq += v * v;
    }
#pragma unroll
    for (int off = 16; off; off >>= 1) {
        s  += __shfl_xor_sync(0xffffffffu, s,  off);
        sq += __shfl_xor_sync(0xffffffffu, sq, off);
    }
    __shared__ float rs[8], rq[8];
    int w = tid >> 5, lane = tid & 31;
    if (!lane) { rs[w] = s; rq[w] = sq; }
    __syncthreads();
    s = 0.f; sq = 0.f;
#pragma unroll
    for (int i = 0; i < 8; i++) { s += rs[i]; sq += rq[i]; }
    float mean = s / (float)CH;
    float var  = sq / (float)CH - mean * mean;
    float inv  = rsqrtf(var + EPSV);
    for (int i = tid; i < CH; i += 256) {
        int dch = g * 8 + i / 3072;
        float v = (g_conv1[base + i] - mean) * inv * gamma[dch] + beta[dch];
        split2(v, &g_xnh[base + i], &g_xnl[base + i]);
    }
}

// ---------------- 4) q GEMM via mma: C[4096][256] = xn[4096][384] @ weff^T ------
__global__ void __launch_bounds__(256) k_qmma(const float* __restrict__ b1,
                                              const float* __restrict__ w2,
                                              const float* __restrict__ b2) {
    int n0 = blockIdx.x * 128, o0 = blockIdx.y * 64;
    int tid = threadIdx.x, lane = tid & 31, warp = tid >> 5;
    int q2 = (lane & 3) * 2, gp = lane >> 2;
    float acc[8][4];
#pragma unroll
    for (int a = 0; a < 8; a++)
#pragma unroll
        for (int c = 0; c < 4; c++) acc[a][c] = 0.f;

    const __nv_bfloat16* Ah = g_xnh + (size_t)(n0 + warp * 16 + gp) * 384 + q2;
    const __nv_bfloat16* Al = g_xnl + (size_t)(n0 + warp * 16 + gp) * 384 + q2;

    for (int kk = 0; kk < 384; kk += 16) {
        unsigned a0 = ldb2(Ah + kk),            a1 = ldb2(Ah + 8 * 384 + kk);
        unsigned a2 = ldb2(Ah + kk + 8),        a3 = ldb2(Ah + 8 * 384 + kk + 8);
        unsigned l0 = ldb2(Al + kk),            l1 = ldb2(Al + 8 * 384 + kk);
        unsigned l2 = ldb2(Al + kk + 8),        l3 = ldb2(Al + 8 * 384 + kk + 8);
#pragma unroll
        for (int nt = 0; nt < 8; nt++) {
            const __nv_bfloat16* Bh = g_wqh + (size_t)(o0 + nt * 8 + gp) * 384 + q2 + kk;
            const __nv_bfloat16* Bl = g_wql + (size_t)(o0 + nt * 8 + gp) * 384 + q2 + kk;
            unsigned bh0 = ldb2(Bh), bh1 = ldb2(Bh + 8);
            unsigned bl0 = ldb2(Bl), bl1 = ldb2(Bl + 8);
            mma16816(acc[nt], a0, a1, a2, a3, bh0, bh1);
            mma16816(acc[nt], l0, l1, l2, l3, bh0, bh1);
            mma16816(acc[nt], a0, a1, a2, a3, bl0, bl1);
        }
    }
    float sws = w2[0] + w2[1] + w2[2];
    float fb = b2[0];
    int n = n0 + warp * 16 + gp;
#pragma unroll
    for (int nt = 0; nt < 8; nt++) {
        int o = o0 + nt * 8 + q2;
        g_q[n * 256 + o]           = acc[nt][0] + b1[o] * sws + fb;
        g_q[n * 256 + o + 1]       = acc[nt][1] + b1[o + 1] * sws + fb;
        g_q[(n + 8) * 256 + o]     = acc[nt][2] + b1[o] * sws + fb;
        g_q[(n + 8) * 256 + o + 1] = acc[nt][3] + b1[o + 1] * sws + fb;
    }
}

// ---------------- 5) attention (one block per row r) ----------------------------
__global__ void k_attn(const float* __restrict__ kc, const float* __restrict__ vc) {
    int r = blockIdx.x;
    int tid = threadIdx.x;     // 128
    int w = tid >> 5, lane = tid & 31;
    __shared__ float sq[64];
    __shared__ float se[128];
    __shared__ float red[4], red2[4];
    __shared__ float oacc[4][32];

    if (tid < 64) sq[tid] = g_q[r * 64 + tid];
    __syncthreads();

    const float4* krow = (const float4*)(kc + (size_t)r * 8192 + (size_t)tid * 64);
    float dot = 0.f;
#pragma unroll
    for (int i = 0; i < 16; i++) {
        float4 kv = krow[i];
        dot += kv.x * sq[i * 4] + kv.y * sq[i * 4 + 1] + kv.z * sq[i * 4 + 2] + kv.w * sq[i * 4 + 3];
    }
    dot *= 0.125f;

    float m = dot;
#pragma unroll
    for (int off = 16; off; off >>= 1) m = fmaxf(m, __shfl_xor_sync(0xffffffffu, m, off));
    if (!lane) red[w] = m;
    __syncthreads();
    m = fmaxf(fmaxf(red[0], red[1]), fmaxf(red[2], red[3]));

    float e = __expf(dot - m);
    se[tid] = e;
    float s = e;
#pragma unroll
    for (int off = 16; off; off >>= 1) s += __shfl_xor_sync(0xffffffffu, s, off);
    if (!lane) red2[w] = s;
    __syncthreads();
    float inv = 1.f / (red2[0] + red2[1] + red2[2] + red2[3]);

    const float* vbase = vc + (size_t)r * 4096;
    float a = 0.f;
#pragma unroll 4
    for (int li = 0; li < 32; li++) {
        int l = w * 32 + li;
        a = fmaf(se[l], vbase[l * 32 + lane], a);
    }
    oacc[w][lane] = a;
    __syncthreads();
    if (tid < 32) {
        float tot = (oacc[0][tid] + oacc[1][tid] + oacc[2][tid] + oacc[3][tid]) * inv;
        int lin = (r & 4095) * 128 + (r >> 12) * 32 + tid;   // (Nq,DC) flat index
        int bb = lin >> 17;
        int C  = (lin >> 10) & 127;
        int hw = lin & 1023;
        size_t d = ((size_t)(bb * 1024 + hw)) * 128 + C;     // transposed [b][hw][C]
        split2(tot, &g_oah[d], &g_oal[d]);
    }
}

// ---------------- 6) out projection via mma -> padded conv2 input ---------------
__global__ void __launch_bounds__(256) k_omma(const float* __restrict__ bias) {
    int hw0 = blockIdx.x * 64, b = blockIdx.y;
    int tid = threadIdx.x, lane = tid & 31, warp = tid >> 5;
    int q2 = (lane & 3) * 2, gp = lane >> 2;
    float acc[8][4];
#pragma unroll
    for (int a = 0; a < 8; a++)
#pragma unroll
        for (int c = 0; c < 4; c++) acc[a][c] = 0.f;

    const __nv_bfloat16* Ah = g_woh + (size_t)(warp * 16 + gp) * 128 + q2;
    const __nv_bfloat16* Al = g_wol + (size_t)(warp * 16 + gp) * 128 + q2;

    for (int kk = 0; kk < 128; kk += 16) {
        unsigned a0 = ldb2(Ah + kk),            a1 = ldb2(Ah + 8 * 128 + kk);
        unsigned a2 = ldb2(Ah + kk + 8),        a3 = ldb2(Ah + 8 * 128 + kk + 8);
        unsigned l0 = ldb2(Al + kk),            l1 = ldb2(Al + 8 * 128 + kk);
        unsigned l2 = ldb2(Al + kk + 8),        l3 = ldb2(Al + 8 * 128 + kk + 8);
#pragma unroll
        for (int nt = 0; nt < 8; nt++) {
            const __nv_bfloat16* Bh = g_oah + ((size_t)b * 1024 + hw0 + nt * 8 + gp) * 128 + q2 + kk;
            const __nv_bfloat16* Bl = g_oal + ((size_t)b * 1024 + hw0 + nt * 8 + gp) * 128 + q2 + kk;
            unsigned bh0 = ldb2(Bh), bh1 = ldb2(Bh + 8);
            unsigned bl0 = ldb2(Bl), bl1 = ldb2(Bl + 8);
            mma16816(acc[nt], a0, a1, a2, a3, bh0, bh1);
            mma16816(acc[nt], l0, l1, l2, l3, bh0, bh1);
            mma16816(acc[nt], a0, a1, a2, a3, bl0, bl1);
        }
    }
    int o = warp * 16 + gp;
    float bv0 = bias[o], bv1 = bias[o + 8];
#pragma unroll
    for (int nt = 0; nt < 8; nt++) {
        int hw = hw0 + nt * 8 + q2;
        int y = hw >> 5, x = hw & 31;
        size_t d0 = ((size_t)(b * 128 + o) * 34 + y + 1) * 34 + x + 1;
        size_t d1 = ((size_t)(b * 128 + o + 8) * 34 + y + 1) * 34 + x + 1;
        split2(acc[nt][0] + bv0, &g_o2h[d0],     &g_o2l[d0]);
        split2(acc[nt][1] + bv0, &g_o2h[d0 + 1], &g_o2l[d0 + 1]);
        split2(acc[nt][2] + bv1, &g_o2h[d1],     &g_o2l[d1]);
        split2(acc[nt][3] + bv1, &g_o2h[d1 + 1], &g_o2l[d1 + 1]);
    }
}

// ---------------- 8) modulation -------------------------------------------------
__global__ void k_cmod(const float* __restrict__ emb, const float* __restrict__ mw,
                       const float* __restrict__ mb) {
    int t = threadIdx.x;
    if (t >= 56) return;
    int b = t / 14, j = t % 14;
    float acc = mb[j];
    for (int i = 0; i < 256; i++) {
        float v = emb[b * 256 + i];
        float sil = v / (1.f + __expf(-v));
        acc = fmaf(sil, mw[j * 256 + i], acc);
    }
    g_cmod[t] = acc;
}

// ---------------- 9/10) per-batch stats of u ------------------------------------
__global__ void k_upart() {
    int b = blockIdx.y, blk = blockIdx.x;
    size_t base = (size_t)b * 458752 + (size_t)blk * 14336;
    int tid = threadIdx.x;
    float s = 0.f, sq = 0.f;
    for (int i = tid; i < 14336; i += 256) {
        float v = g_u[base + i];
        s += v; sq += v * v;
    }
#pragma unroll
    for (int off = 16; off; off >>= 1) {
        s  += __shfl_xor_sync(0xffffffffu, s,  off);
        sq += __shfl_xor_sync(0xffffffffu, sq, off);
    }
    __shared__ float rs[8], rq[8];
    int w = tid >> 5, lane = tid & 31;
    if (!lane) { rs[w] = s; rq[w] = sq; }
    __syncthreads();
    if (tid == 0) {
        float ts = 0.f, tq = 0.f;
#pragma unroll
        for (int i = 0; i < 8; i++) { ts += rs[i]; tq += rq[i]; }
        g_psum[b * 32 + blk] = ts;
        g_psq [b * 32 + blk] = tq;
    }
}
__global__ void k_ucomb() {
    int b = threadIdx.x;
    if (b < 4) {
        float s = 0.f, sq = 0.f;
        for (int i = 0; i < 32; i++) { s += g_psum[b * 32 + i]; sq += g_psq[b * 32 + i]; }
        float mean = s / 458752.f;
        float var  = sq / 458752.f - mean * mean;
        g_stats[b * 2]     = mean;
        g_stats[b * 2 + 1] = rsqrtf(var + EPSV);
    }
}

// ---------------- 11) final fused elementwise -----------------------------------
__global__ void k_final(const float* __restrict__ ew, const float* __restrict__ eb,
                        const float* __restrict__ fw, const float* __restrict__ fb,
                        float* __restrict__ out) {
    int b = blockIdx.y;
    int p = blockIdx.x * 256 + threadIdx.x;
    __shared__ float s_ew[98], s_eb[14], s_fw[49], s_fb[7], s_sc[7], s_sh[7];
    __shared__ float s_mean, s_istd;
    int t = threadIdx.x;
    if (t < 98) s_ew[t] = ew[t];
    if (t < 49) s_fw[t] = fw[t];
    if (t < 14) s_eb[t] = eb[t];
    if (t < 7)  { s_fb[t] = fb[t]; s_sc[t] = g_cmod[b * 14 + t]; s_sh[t] = g_cmod[b * 14 + 7 + t]; }
    if (t == 0) { s_mean = g_stats[b * 2]; s_istd = g_stats[b * 2 + 1]; }
    __syncthreads();

    float mean = s_mean, istd = s_istd;
    float uv[7], un[7];
#pragma unroll
    for (int e = 0; e < 7; e++) uv[e] = g_u[((size_t)b * 7 + e) * 65536 + p];
#pragma unroll
    for (int e = 0; e < 7; e++) un[e] = (uv[e] - mean) * istd * (1.f + s_sc[e]) + s_sh[e];

    float en[14];
#pragma unroll
    for (int j = 0; j < 14; j++) {
        float a = s_eb[j];
#pragma unroll
        for (int e = 0; e < 7; e++) a = fmaf(s_ew[j * 7 + e], un[e], a);
        en[j] = a;
    }
    float hf[7];
#pragma unroll
    for (int e = 0; e < 7; e++) hf[e] = geluf(un[e]) + en[e] * geluf(en[7 + e]);

#pragma unroll
    for (int o = 0; o < 7; o++) {
        float a = s_fb[o];
#pragma unroll
        for (int e = 0; e < 7; e++) a = fmaf(s_fw[o * 7 + e], hf[e], a);
        out[((size_t)b * 7 + o) * 65536 + p] = a + uv[o];
    }
}

// ---------------- launch --------------------------------------------------------
extern "C" void kernel_launch(void* const* d_in, const int* in_sizes, int n_in,
                              void* d_out, int out_size) {
    const float* x         = (const float*)d_in[0];
    const float* k_cond    = (const float*)d_in[1];
    const float* v_cond    = (const float*)d_in[2];
    const float* emb       = (const float*)d_in[3];
    const float* pos_embed = (const float*)d_in[4];
    const float* patch_w   = (const float*)d_in[5];
    const float* patch_b   = (const float*)d_in[6];
    const float* gn_gamma  = (const float*)d_in[7];
    const float* gn_beta   = (const float*)d_in[8];
    const float* fc1q_w    = (const float*)d_in[9];
    const float* fc1q_b    = (const float*)d_in[10];
    const float* fc2q_w    = (const float*)d_in[11];
    const float* fc2q_b    = (const float*)d_in[12];
    const float* outproj_w = (const float*)d_in[13];
    const float* outproj_b = (const float*)d_in[14];
    const float* unpatch_w = (const float*)d_in[15];
    const float* unpatch_b = (const float*)d_in[16];
    const float* mod_w     = (const float*)d_in[17];
    const float* mod_b     = (const float*)d_in[18];
    const float* enlarge_w = (const float*)d_in[19];
    const float* enlarge_b = (const float*)d_in[20];
    const float* ff2_w     = (const float*)d_in[21];
    const float* ff2_b     = (const float*)d_in[22];
    float* out = (float*)d_out;

    k_pack  <<<2688, 256>>>(x);
    k_packw1<<<(9*128*448 + 255) / 256, 256>>>(patch_w);
    k_packw2<<<(9*448*128 + 255) / 256, 256>>>(unpatch_w);
    k_packwq<<<384, 256>>>(fc1q_w, fc2q_w);
    k_packwo<<<64, 256>>>(outproj_w);

    k_convmma<448, 128, 8, 8, 2, 1><<<dim3(16, 1, 12), 256>>>(patch_b, pos_embed);
    k_gnorm<<<64, 256>>>(gn_gamma, gn_beta);
    k_qmma<<<dim3(32, 4), 256>>>(fc1q_b, fc2q_w, fc2q_b);
    k_attn<<<16384, 128>>>(k_cond, v_cond);
    k_omma<<<dim3(16, 4), 256>>>(outproj_b);
    k_convmma<128, 448, 7, 8, 2, 2><<<dim3(16, 4, 4), 224>>>(unpatch_b, (const float*)0);

    k_cmod<<<1, 64>>>(emb, mod_w, mod_b);
    k_upart<<<dim3(32, 4), 256>>>();
    k_ucomb<<<1, 32>>>();
    k_final<<<dim3(256, 4), 256>>>(enlarge_w, enlarge_b, ff2_w, ff2_b, out);
}